// round 13
// baseline (speedup 1.0000x reference)
#include <cuda_runtime.h>

#define NU     1000000
#define NI     100000
#define E_     16
#define O_     16
#define H_     4
#define HID_   32
#define B_     8192
#define S_     200
#define L_     50
#define NSUPP_ 50000

// Scratch (static __device__ arrays — no runtime allocation)
__device__ float d_q[H_ * B_ * O_];          // 2 MB   q[h][b][o]
__device__ float d_ksupp[H_ * NSUPP_ * O_];  // 12.8MB k_supp[h][i][o]
__device__ float d_gat[B_ * H_ * O_];        // 2 MB   gat[b][h*16+o]

// ---------------------------------------------------------------------------
// Kernel 0: user_init[b] = sum_l item_emb[history[b,l]] / len[b];
//           q[h,b,o] = sum_e user_init[b,e] * wq[h,e,o]
// One warp per b. Lane layout: o = lane%16, g = lane/16 splits the L loop.
// ---------------------------------------------------------------------------
__global__ void k0_userinit_q(const float* __restrict__ item_emb,
                              const int*   __restrict__ history,
                              const int*   __restrict__ hist_len,
                              const float* __restrict__ wq) {
    __shared__ float sm_ui[8][16];
    const int warp = threadIdx.x >> 5;
    const int lane = threadIdx.x & 31;
    const int b    = blockIdx.x * 8 + warp;
    const int o    = lane & 15;
    const int g    = lane >> 4;

    const int* hrow = history + (size_t)b * L_;
    float acc = 0.f;
    for (int l = g; l < L_; l += 2) {
        int idx = __ldg(&hrow[l]);
        acc += __ldg(&item_emb[(size_t)idx * 16 + o]);
    }
    acc += __shfl_xor_sync(0xffffffffu, acc, 16);
    float inv_len = 1.0f / (float)__ldg(&hist_len[b]);
    if (g == 0) sm_ui[warp][o] = acc * inv_len;
    __syncwarp();

    // q: lane handles (o, heads {g, g+2})
    #pragma unroll
    for (int hh = 0; hh < 2; hh++) {
        int h = g + hh * 2;
        float q = 0.f;
        #pragma unroll
        for (int e = 0; e < 16; e++)
            q += sm_ui[warp][e] * __ldg(&wq[(h * 16 + e) * 16 + o]);
        d_q[((size_t)h * B_ + b) * 16 + o] = q;
    }
}

// ---------------------------------------------------------------------------
// Kernel 1: k_supp[h,i,o] = sum_e user_emb[supp_users[i], e] * wk[h,e,o]
// One thread per (h,i). wk staged in smem (broadcast reads).
// ---------------------------------------------------------------------------
__global__ void k1_ksupp(const float* __restrict__ user_emb,
                         const int*   __restrict__ supp_users,
                         const float* __restrict__ wk) {
    __shared__ float sm_wk[H_ * 256];
    for (int i = threadIdx.x; i < H_ * 256; i += blockDim.x) sm_wk[i] = wk[i];
    __syncthreads();

    int t = blockIdx.x * blockDim.x + threadIdx.x;
    if (t >= H_ * NSUPP_) return;
    int i = t % NSUPP_;
    int h = t / NSUPP_;

    int u = __ldg(&supp_users[i]);
    const float4* erow = (const float4*)(user_emb + (size_t)u * 16);
    float emb[16];
    ((float4*)emb)[0] = __ldg(erow + 0);
    ((float4*)emb)[1] = __ldg(erow + 1);
    ((float4*)emb)[2] = __ldg(erow + 2);
    ((float4*)emb)[3] = __ldg(erow + 3);

    const float* W = sm_wk + h * 256;
    float out[16];
    #pragma unroll
    for (int o = 0; o < 16; o++) {
        float acc = 0.f;
        #pragma unroll
        for (int e = 0; e < 16; e++) acc += emb[e] * W[e * 16 + o];
        out[o] = acc;
    }
    float4* dst = (float4*)(d_ksupp + ((size_t)h * NSUPP_ + i) * 16);
    dst[0] = ((float4*)out)[0];
    dst[1] = ((float4*)out)[1];
    dst[2] = ((float4*)out)[2];
    dst[3] = ((float4*)out)[3];
}

// ---------------------------------------------------------------------------
// Kernel 2: attention + gat. One warp per (h,b).
// Lane layout: sg = lane/4 (8 s-entries per step), comp = lane%4 (float4 of k).
// Online softmax: single gather pass over k_supp (L2-resident).
// ---------------------------------------------------------------------------
__global__ void k2_attn(const int*   __restrict__ sample_index,
                        const float* __restrict__ wv) {
    __shared__ float sm_wv[H_ * 256];
    for (int i = threadIdx.x; i < H_ * 256; i += blockDim.x) sm_wv[i] = wv[i];
    __syncthreads();

    const int warp = threadIdx.x >> 5;
    const int lane = threadIdx.x & 31;
    const int w    = blockIdx.x * 8 + warp;   // 0 .. H*B-1
    const int h    = w / B_;
    const int b    = w % B_;
    const int sg   = lane >> 2;
    const int comp = lane & 3;

    const float4 qv = *(const float4*)(d_q + ((size_t)h * B_ + b) * 16 + comp * 4);
    const int*   sidx = sample_index + ((size_t)h * B_ + b) * S_;
    const float* ktab = d_ksupp + (size_t)h * NSUPP_ * 16;

    float m = -1e30f, lsum = 0.f;
    float c0 = 0.f, c1 = 0.f, c2 = 0.f, c3 = 0.f;

    #pragma unroll 5
    for (int s0 = 0; s0 < S_; s0 += 8) {
        int s   = s0 + sg;
        int idx = __ldg(&sidx[s]);
        float4 kv = *(const float4*)(ktab + (size_t)idx * 16 + comp * 4);
        float d = kv.x * qv.x + kv.y * qv.y + kv.z * qv.z + kv.w * qv.w;
        d += __shfl_xor_sync(0xffffffffu, d, 1);
        d += __shfl_xor_sync(0xffffffffu, d, 2);
        float mn   = fmaxf(m, d);
        float corr = __expf(m - mn);
        float p    = __expf(d - mn);
        lsum = lsum * corr + p;
        c0 = c0 * corr + p * kv.x;
        c1 = c1 * corr + p * kv.y;
        c2 = c2 * corr + p * kv.z;
        c3 = c3 * corr + p * kv.w;
        m = mn;
    }

    // Merge the 8 subgroup softmax states (xor 4, 8, 16)
    #pragma unroll
    for (int off = 4; off <= 16; off <<= 1) {
        float mo = __shfl_xor_sync(0xffffffffu, m,    off);
        float lo = __shfl_xor_sync(0xffffffffu, lsum, off);
        float d0 = __shfl_xor_sync(0xffffffffu, c0,   off);
        float d1 = __shfl_xor_sync(0xffffffffu, c1,   off);
        float d2 = __shfl_xor_sync(0xffffffffu, c2,   off);
        float d3 = __shfl_xor_sync(0xffffffffu, c3,   off);
        float mn = fmaxf(m, mo);
        float a  = __expf(m  - mn);
        float bb = __expf(mo - mn);
        lsum = lsum * a + lo * bb;
        c0 = c0 * a + d0 * bb;
        c1 = c1 * a + d1 * bb;
        c2 = c2 * a + d2 * bb;
        c3 = c3 * a + d3 * bb;
        m = mn;
    }
    float inv = 1.0f / lsum;
    c0 *= inv; c1 *= inv; c2 *= inv; c3 *= inv;

    // Assemble full 16-dim ctx in every lane (lane c<4 holds comps [4c,4c+4))
    float ctx[16];
    #pragma unroll
    for (int c = 0; c < 4; c++) {
        ctx[c * 4 + 0] = __shfl_sync(0xffffffffu, c0, c);
        ctx[c * 4 + 1] = __shfl_sync(0xffffffffu, c1, c);
        ctx[c * 4 + 2] = __shfl_sync(0xffffffffu, c2, c);
        ctx[c * 4 + 3] = __shfl_sync(0xffffffffu, c3, c);
    }

    // gat[h,b,p] = sum_o ctx[o] * wv[h,o,p]   (lanes 0..15 compute p = lane)
    if (lane < 16) {
        const float* Wv = sm_wv + h * 256;
        float g = 0.f;
        #pragma unroll
        for (int e = 0; e < 16; e++) g += ctx[e] * Wv[e * 16 + lane];
        d_gat[(size_t)b * 64 + h * 16 + lane] = g;
    }
}

// ---------------------------------------------------------------------------
// Kernel 3: user_emb = gat@w_out; interaction; fused MLP; biases; output.
// One thread per b; all weights staged in smem (lockstep broadcast reads).
// ---------------------------------------------------------------------------
__global__ void k3_final(const float* __restrict__ item_emb,
                         const float* __restrict__ w_out,
                         const float* __restrict__ l1_w, const float* __restrict__ l1_b,
                         const float* __restrict__ l2_w, const float* __restrict__ l2_b,
                         const float* __restrict__ l3_w, const float* __restrict__ l3_b,
                         const float* __restrict__ user_bias,
                         const float* __restrict__ item_bias,
                         const int*   __restrict__ x,
                         float*       __restrict__ out) {
    __shared__ float sm_wout[64 * 16];
    __shared__ float sm_l1w[48 * 32];
    __shared__ float sm_l2w[32 * 16];
    __shared__ float sm_l3w[16];
    __shared__ float sm_l1b[32];
    __shared__ float sm_l2b[16];
    __shared__ float sm_l3b;
    for (int i = threadIdx.x; i < 1024; i += 256) sm_wout[i] = w_out[i];
    for (int i = threadIdx.x; i < 1536; i += 256) sm_l1w[i]  = l1_w[i];
    for (int i = threadIdx.x; i < 512;  i += 256) sm_l2w[i]  = l2_w[i];
    if (threadIdx.x < 16)                        sm_l3w[threadIdx.x]      = l3_w[threadIdx.x];
    if (threadIdx.x >= 16 && threadIdx.x < 48)   sm_l1b[threadIdx.x - 16] = l1_b[threadIdx.x - 16];
    if (threadIdx.x >= 48 && threadIdx.x < 64)   sm_l2b[threadIdx.x - 48] = l2_b[threadIdx.x - 48];
    if (threadIdx.x == 64)                       sm_l3b                   = l3_b[0];
    __syncthreads();

    const int b   = blockIdx.x * blockDim.x + threadIdx.x;
    const int uid = __ldg(&x[b * 2]);
    const int iid = __ldg(&x[b * 2 + 1]);

    // user_emb = gat_row(64) @ w_out(64x16)
    float ue[16];
    #pragma unroll
    for (int o = 0; o < 16; o++) ue[o] = 0.f;
    const float* grow = d_gat + (size_t)b * 64;
    #pragma unroll 4
    for (int j = 0; j < 64; j++) {
        float gj = grow[j];
        #pragma unroll
        for (int o = 0; o < 16; o++) ue[o] += gj * sm_wout[j * 16 + o];
    }

    float ie[16];
    const float4* ir = (const float4*)(item_emb + (size_t)iid * 16);
    ((float4*)ie)[0] = __ldg(ir + 0);
    ((float4*)ie)[1] = __ldg(ir + 1);
    ((float4*)ie)[2] = __ldg(ir + 2);
    ((float4*)ie)[3] = __ldg(ir + 3);

    float it[16], rating = 0.f;
    #pragma unroll
    for (int o = 0; o < 16; o++) { it[o] = ue[o] * ie[o]; rating += it[o]; }

    float x1[32];
    #pragma unroll 4
    for (int k = 0; k < 32; k++) {
        float acc = sm_l1b[k];
        #pragma unroll
        for (int j = 0; j < 16; j++)
            acc += ue[j] * sm_l1w[j * 32 + k]
                 + ie[j] * sm_l1w[(16 + j) * 32 + k]
                 + it[j] * sm_l1w[(32 + j) * 32 + k];
        x1[k] = tanhf(acc);
    }

    float x2[16];
    #pragma unroll 4
    for (int k = 0; k < 16; k++) {
        float acc = sm_l2b[k];
        #pragma unroll
        for (int j = 0; j < 32; j++) acc += x1[j] * sm_l2w[j * 16 + k];
        x2[k] = tanhf(acc);
    }

    float x3 = sm_l3b;
    #pragma unroll
    for (int j = 0; j < 16; j++) x3 += x2[j] * sm_l3w[j];

    out[b] = 0.5f * (rating + x3) + __ldg(&user_bias[uid]) + __ldg(&item_bias[iid]);
}

// ---------------------------------------------------------------------------
extern "C" void kernel_launch(void* const* d_in, const int* in_sizes, int n_in,
                              void* d_out, int out_size) {
    (void)in_sizes; (void)n_in; (void)out_size;
    const float* user_embedding = (const float*)d_in[0];
    const float* item_embedding = (const float*)d_in[1];
    const float* wq             = (const float*)d_in[2];
    const float* wk             = (const float*)d_in[3];
    const float* wv             = (const float*)d_in[4];
    const float* w_out          = (const float*)d_in[5];
    const float* l1_w           = (const float*)d_in[6];
    const float* l1_b           = (const float*)d_in[7];
    const float* l2_w           = (const float*)d_in[8];
    const float* l2_b           = (const float*)d_in[9];
    const float* l3_w           = (const float*)d_in[10];
    const float* l3_b           = (const float*)d_in[11];
    const float* user_bias      = (const float*)d_in[12];
    const float* item_bias      = (const float*)d_in[13];
    const int*   x              = (const int*)d_in[14];
    const int*   history        = (const int*)d_in[15];
    const int*   history_len    = (const int*)d_in[16];
    const int*   supp_users     = (const int*)d_in[17];
    const int*   sample_index   = (const int*)d_in[18];
    float* out = (float*)d_out;

    k0_userinit_q<<<B_ / 8, 256>>>(item_embedding, history, history_len, wq);
    k1_ksupp<<<(H_ * NSUPP_ + 255) / 256, 256>>>(user_embedding, supp_users, wk);
    k2_attn<<<(H_ * B_) / 8, 256>>>(sample_index, wv);
    k3_final<<<B_ / 256, 256>>>(item_embedding, w_out,
                                l1_w, l1_b, l2_w, l2_b, l3_w, l3_b,
                                user_bias, item_bias, x, out);
}

// round 14
// speedup vs baseline: 1.1938x; 1.1938x over previous
#include <cuda_runtime.h>
#include <cuda_fp16.h>

#define NU     1000000
#define NI     100000
#define E_     16
#define O_     16
#define H_     4
#define HID_   32
#define B_     8192
#define S_     200
#define L_     50
#define NSUPP_ 50000

// Scratch (static __device__ arrays — no runtime allocation)
__device__ float d_q[H_ * B_ * O_];                         // 2 MB    q[h][b][o]
__device__ __align__(16) __half2 d_ksupp[H_ * NSUPP_ * 8];  // 6.4 MB  k_supp[h][i][o] fp16
__device__ float d_gat[B_ * H_ * O_];                       // 2 MB    gat[b][h*16+o]

__device__ __forceinline__ float tanhfast(float x) {
    float y;
    asm("tanh.approx.f32 %0, %1;" : "=f"(y) : "f"(x));
    return y;
}

// ---------------------------------------------------------------------------
// Fused kernel 0+1 (independent block ranges):
//  blocks [0, B/8):        user_init + q   (one warp per b)
//  blocks [B/8, ...):      k_supp[h,i,:] = user_emb[supp[i]] @ wk[h]  (fp16 out)
// ---------------------------------------------------------------------------
#define K0_BLOCKS (B_ / 8)
#define K1_BLOCKS ((H_ * NSUPP_ + 255) / 256)

__global__ void k01_setup(const float* __restrict__ item_emb,
                          const int*   __restrict__ history,
                          const int*   __restrict__ hist_len,
                          const float* __restrict__ wq,
                          const float* __restrict__ user_emb,
                          const int*   __restrict__ supp_users,
                          const float* __restrict__ wk) {
    __shared__ float sm[H_ * 256];   // wk for k1-part; unused by k0-part
    __shared__ float sm_ui[8][16];

    if (blockIdx.x < K0_BLOCKS) {
        // ---- k0: user_init + q ----
        const int warp = threadIdx.x >> 5;
        const int lane = threadIdx.x & 31;
        const int b    = blockIdx.x * 8 + warp;
        const int o    = lane & 15;
        const int g    = lane >> 4;

        const int* hrow = history + (size_t)b * L_;
        float acc = 0.f;
        for (int l = g; l < L_; l += 2) {
            int idx = __ldg(&hrow[l]);
            acc += __ldg(&item_emb[(size_t)idx * 16 + o]);
        }
        acc += __shfl_xor_sync(0xffffffffu, acc, 16);
        float inv_len = 1.0f / (float)__ldg(&hist_len[b]);
        if (g == 0) sm_ui[warp][o] = acc * inv_len;
        __syncwarp();

        #pragma unroll
        for (int hh = 0; hh < 2; hh++) {
            int h = g + hh * 2;
            float q = 0.f;
            #pragma unroll
            for (int e = 0; e < 16; e++)
                q += sm_ui[warp][e] * __ldg(&wq[(h * 16 + e) * 16 + o]);
            d_q[((size_t)h * B_ + b) * 16 + o] = q;
        }
    } else {
        // ---- k1: k_supp (fp16) ----
        for (int i = threadIdx.x; i < H_ * 256; i += blockDim.x) sm[i] = wk[i];
        __syncthreads();

        int t = (blockIdx.x - K0_BLOCKS) * blockDim.x + threadIdx.x;
        if (t >= H_ * NSUPP_) return;
        int i = t % NSUPP_;
        int h = t / NSUPP_;

        int u = __ldg(&supp_users[i]);
        const float4* erow = (const float4*)(user_emb + (size_t)u * 16);
        float emb[16];
        ((float4*)emb)[0] = __ldg(erow + 0);
        ((float4*)emb)[1] = __ldg(erow + 1);
        ((float4*)emb)[2] = __ldg(erow + 2);
        ((float4*)emb)[3] = __ldg(erow + 3);

        const float* W = sm + h * 256;
        float out[16];
        #pragma unroll
        for (int o = 0; o < 16; o++) {
            float acc = 0.f;
            #pragma unroll
            for (int e = 0; e < 16; e++) acc += emb[e] * W[e * 16 + o];
            out[o] = acc;
        }
        __half2 oh[8];
        #pragma unroll
        for (int p = 0; p < 8; p++)
            oh[p] = __floats2half2_rn(out[2 * p], out[2 * p + 1]);
        uint4* dst = (uint4*)(d_ksupp + ((size_t)h * NSUPP_ + i) * 8);
        dst[0] = *(uint4*)&oh[0];
        dst[1] = *(uint4*)&oh[4];
    }
}

// ---------------------------------------------------------------------------
// Kernel 2: attention + gat. One warp per (h,b).
// Lane layout: sg = lane/4 (8 s-entries/step), comp = lane%4 (8B of fp16 k).
// Online softmax, single gather pass; k-table (6.4 MB) is L2-resident.
// ---------------------------------------------------------------------------
__global__ void k2_attn(const int*   __restrict__ sample_index,
                        const float* __restrict__ wv) {
    __shared__ float sm_wv[H_ * 256];
    for (int i = threadIdx.x; i < H_ * 256; i += blockDim.x) sm_wv[i] = wv[i];
    __syncthreads();

    const int warp = threadIdx.x >> 5;
    const int lane = threadIdx.x & 31;
    const int w    = blockIdx.x * 8 + warp;   // 0 .. H*B-1
    const int h    = w / B_;
    const int b    = w % B_;
    const int sg   = lane >> 2;
    const int comp = lane & 3;

    const float4 qv = *(const float4*)(d_q + ((size_t)h * B_ + b) * 16 + comp * 4);
    const int*     sidx = sample_index + ((size_t)h * B_ + b) * S_;
    const __half2* ktab = d_ksupp + (size_t)h * NSUPP_ * 8;

    float m = -1e30f, lsum = 0.f;
    float c0 = 0.f, c1 = 0.f, c2 = 0.f, c3 = 0.f;

    #pragma unroll 5
    for (int s0 = 0; s0 < S_; s0 += 8) {
        int s   = s0 + sg;
        int idx = __ldg(&sidx[s]);
        uint2 raw = *(const uint2*)(ktab + (size_t)idx * 8 + comp * 2);
        float2 f0 = __half22float2(*(__half2*)&raw.x);
        float2 f1 = __half22float2(*(__half2*)&raw.y);
        float d = f0.x * qv.x + f0.y * qv.y + f1.x * qv.z + f1.y * qv.w;
        d += __shfl_xor_sync(0xffffffffu, d, 1);
        d += __shfl_xor_sync(0xffffffffu, d, 2);
        float mn   = fmaxf(m, d);
        float corr = __expf(m - mn);
        float p    = __expf(d - mn);
        lsum = lsum * corr + p;
        c0 = c0 * corr + p * f0.x;
        c1 = c1 * corr + p * f0.y;
        c2 = c2 * corr + p * f1.x;
        c3 = c3 * corr + p * f1.y;
        m = mn;
    }

    // Merge the 8 subgroup softmax states (xor 4, 8, 16)
    #pragma unroll
    for (int off = 4; off <= 16; off <<= 1) {
        float mo = __shfl_xor_sync(0xffffffffu, m,    off);
        float lo = __shfl_xor_sync(0xffffffffu, lsum, off);
        float d0 = __shfl_xor_sync(0xffffffffu, c0,   off);
        float d1 = __shfl_xor_sync(0xffffffffu, c1,   off);
        float d2 = __shfl_xor_sync(0xffffffffu, c2,   off);
        float d3 = __shfl_xor_sync(0xffffffffu, c3,   off);
        float mn = fmaxf(m, mo);
        float a  = __expf(m  - mn);
        float bb = __expf(mo - mn);
        lsum = lsum * a + lo * bb;
        c0 = c0 * a + d0 * bb;
        c1 = c1 * a + d1 * bb;
        c2 = c2 * a + d2 * bb;
        c3 = c3 * a + d3 * bb;
        m = mn;
    }
    float inv = 1.0f / lsum;
    c0 *= inv; c1 *= inv; c2 *= inv; c3 *= inv;

    // Assemble full 16-dim ctx in every lane
    float ctx[16];
    #pragma unroll
    for (int c = 0; c < 4; c++) {
        ctx[c * 4 + 0] = __shfl_sync(0xffffffffu, c0, c);
        ctx[c * 4 + 1] = __shfl_sync(0xffffffffu, c1, c);
        ctx[c * 4 + 2] = __shfl_sync(0xffffffffu, c2, c);
        ctx[c * 4 + 3] = __shfl_sync(0xffffffffu, c3, c);
    }

    // gat[h,b,p] = sum_o ctx[o] * wv[h,o,p]   (lanes 0..15 compute p = lane)
    if (lane < 16) {
        const float* Wv = sm_wv + h * 256;
        float g = 0.f;
        #pragma unroll
        for (int e = 0; e < 16; e++) g += ctx[e] * Wv[e * 16 + lane];
        d_gat[(size_t)b * 64 + h * 16 + lane] = g;
    }
}

// ---------------------------------------------------------------------------
// Kernel 3: 4 lanes per b (quad). Lane j owns gat[j*16 .. j*16+16).
// ue: partial + quad butterfly reduce. x1: lane owns 8 of 32 outputs.
// x2: partial over own x1 + reduce. tanh via HW tanh.approx.
// grid = B/64 = 128 blocks of 256 threads -> 32768 threads, 128 SMs busy.
// ---------------------------------------------------------------------------
__global__ void k3_final(const float* __restrict__ item_emb,
                         const float* __restrict__ w_out,
                         const float* __restrict__ l1_w, const float* __restrict__ l1_b,
                         const float* __restrict__ l2_w, const float* __restrict__ l2_b,
                         const float* __restrict__ l3_w, const float* __restrict__ l3_b,
                         const float* __restrict__ user_bias,
                         const float* __restrict__ item_bias,
                         const int*   __restrict__ x,
                         float*       __restrict__ out) {
    __shared__ float sm_wout[64 * 17];   // padded rows: [row][17]
    __shared__ float sm_l1w[48 * 32];
    __shared__ float sm_l2w[32 * 17];    // padded rows
    __shared__ float sm_l3w[16];
    __shared__ float sm_l1b[32];
    __shared__ float sm_l2b[16];
    __shared__ float sm_l3b;
    for (int i = threadIdx.x; i < 1024; i += 256) sm_wout[(i >> 4) * 17 + (i & 15)] = w_out[i];
    for (int i = threadIdx.x; i < 1536; i += 256) sm_l1w[i] = l1_w[i];
    for (int i = threadIdx.x; i < 512;  i += 256) sm_l2w[(i >> 4) * 17 + (i & 15)] = l2_w[i];
    if (threadIdx.x < 16)                      sm_l3w[threadIdx.x]      = l3_w[threadIdx.x];
    if (threadIdx.x >= 16 && threadIdx.x < 48) sm_l1b[threadIdx.x - 16] = l1_b[threadIdx.x - 16];
    if (threadIdx.x >= 48 && threadIdx.x < 64) sm_l2b[threadIdx.x - 48] = l2_b[threadIdx.x - 48];
    if (threadIdx.x == 64)                     sm_l3b                   = l3_b[0];
    __syncthreads();

    const int j = threadIdx.x & 3;                       // lane within quad
    const int b = blockIdx.x * 64 + (threadIdx.x >> 2);  // one b per quad
    const int iid = __ldg(&x[b * 2 + 1]);

    // gat chunk: lane j loads gat[b][j*16 .. j*16+16)  (64B per lane, coalesced)
    float g[16];
    const float4* grow = (const float4*)(d_gat + (size_t)b * 64 + j * 16);
    ((float4*)g)[0] = grow[0];
    ((float4*)g)[1] = grow[1];
    ((float4*)g)[2] = grow[2];
    ((float4*)g)[3] = grow[3];

    // ue partial: sum over this lane's 16 rows of w_out
    float ue[16];
    #pragma unroll
    for (int o = 0; o < 16; o++) ue[o] = 0.f;
    #pragma unroll
    for (int l = 0; l < 16; l++) {
        const float* wrow = sm_wout + (j * 16 + l) * 17;
        float gl = g[l];
        #pragma unroll
        for (int o = 0; o < 16; o++) ue[o] += gl * wrow[o];
    }
    // quad butterfly reduce -> every lane holds full ue[16]
    #pragma unroll
    for (int o = 0; o < 16; o++) {
        ue[o] += __shfl_xor_sync(0xffffffffu, ue[o], 1);
        ue[o] += __shfl_xor_sync(0xffffffffu, ue[o], 2);
    }

    // item embedding (full, broadcast within quad)
    float ie[16];
    const float4* ir = (const float4*)(item_emb + (size_t)iid * 16);
    ((float4*)ie)[0] = __ldg(ir + 0);
    ((float4*)ie)[1] = __ldg(ir + 1);
    ((float4*)ie)[2] = __ldg(ir + 2);
    ((float4*)ie)[3] = __ldg(ir + 3);

    float it[16], rating = 0.f;
    #pragma unroll
    for (int o = 0; o < 16; o++) { it[o] = ue[o] * ie[o]; rating += it[o]; }

    // x1: lane owns outputs k = j*8 .. j*8+8
    float x1[8];
    #pragma unroll
    for (int kk = 0; kk < 8; kk++) {
        int k = j * 8 + kk;
        float acc = sm_l1b[k];
        #pragma unroll
        for (int e = 0; e < 16; e++)
            acc += ue[e] * sm_l1w[e * 32 + k]
                 + ie[e] * sm_l1w[(16 + e) * 32 + k]
                 + it[e] * sm_l1w[(32 + e) * 32 + k];
        x1[kk] = tanhfast(acc);
    }

    // x2 partial over this lane's 8 x1 values
    float x2p[16];
    #pragma unroll
    for (int o = 0; o < 16; o++) x2p[o] = 0.f;
    #pragma unroll
    for (int kk = 0; kk < 8; kk++) {
        int k = j * 8 + kk;
        float v = x1[kk];
        const float* wrow = sm_l2w + k * 17;
        #pragma unroll
        for (int o = 0; o < 16; o++) x2p[o] += v * wrow[o];
    }
    #pragma unroll
    for (int o = 0; o < 16; o++) {
        x2p[o] += __shfl_xor_sync(0xffffffffu, x2p[o], 1);
        x2p[o] += __shfl_xor_sync(0xffffffffu, x2p[o], 2);
    }

    // x3 partial: lane tanh's its 4 of 16 and dots with l3_w
    float x3p = 0.f;
    #pragma unroll
    for (int oo = 0; oo < 4; oo++) {
        int o = j * 4 + oo;
        x3p += tanhfast(x2p[o] + sm_l2b[o]) * sm_l3w[o];
    }
    x3p += __shfl_xor_sync(0xffffffffu, x3p, 1);
    x3p += __shfl_xor_sync(0xffffffffu, x3p, 2);

    if (j == 0) {
        const int uid = __ldg(&x[b * 2]);
        out[b] = 0.5f * (rating + x3p + sm_l3b)
               + __ldg(&user_bias[uid]) + __ldg(&item_bias[iid]);
    }
}

// ---------------------------------------------------------------------------
extern "C" void kernel_launch(void* const* d_in, const int* in_sizes, int n_in,
                              void* d_out, int out_size) {
    (void)in_sizes; (void)n_in; (void)out_size;
    const float* user_embedding = (const float*)d_in[0];
    const float* item_embedding = (const float*)d_in[1];
    const float* wq             = (const float*)d_in[2];
    const float* wk             = (const float*)d_in[3];
    const float* wv             = (const float*)d_in[4];
    const float* w_out          = (const float*)d_in[5];
    const float* l1_w           = (const float*)d_in[6];
    const float* l1_b           = (const float*)d_in[7];
    const float* l2_w           = (const float*)d_in[8];
    const float* l2_b           = (const float*)d_in[9];
    const float* l3_w           = (const float*)d_in[10];
    const float* l3_b           = (const float*)d_in[11];
    const float* user_bias      = (const float*)d_in[12];
    const float* item_bias      = (const float*)d_in[13];
    const int*   x              = (const int*)d_in[14];
    const int*   history        = (const int*)d_in[15];
    const int*   history_len    = (const int*)d_in[16];
    const int*   supp_users     = (const int*)d_in[17];
    const int*   sample_index   = (const int*)d_in[18];
    float* out = (float*)d_out;

    k01_setup<<<K0_BLOCKS + K1_BLOCKS, 256>>>(item_embedding, history, history_len, wq,
                                              user_embedding, supp_users, wk);
    k2_attn<<<(H_ * B_) / 8, 256>>>(sample_index, wv);
    k3_final<<<B_ / 64, 256>>>(item_embedding, w_out,
                               l1_w, l1_b, l2_w, l2_b, l3_w, l3_b,
                               user_bias, item_bias, x, out);
}